// round 13
// baseline (speedup 1.0000x reference)
#include <cuda_runtime.h>
#include <math.h>

#define SL 512
#define BB 128
#define HH 1024
#define FT 576
#define MD 512
#define Z4 4096
#define NT (SL*BB)
#define G2 296        // persistent grid: 2 CTAs/SM x 148 SMs (launch_bounds(256,2))

typedef unsigned long long u64t;

// ---------------- static device scratch ----------------
static __device__ __align__(16) float g_X  [(size_t)NT*FT];
static __device__ __align__(16) float g_pmx[(size_t)NT*HH];   // X@Wmx1^T
static __device__ __align__(16) float g_pih[(size_t)NT*Z4];   // X@Wih1^T + b1
static __device__ __align__(16) float g_d  [(size_t)NT];      // (X@Wsi^T+b_bd)·vs
static __device__ __align__(16) float g_w  [FT];
static __device__ __align__(16) float g_u  [HH];
static __device__ float g_c0[1];
static __device__ __align__(16) float g_h1[BB*HH], g_c1[BB*HH], g_h2[BB*HH], g_c2[BB*HH];
static __device__ __align__(16) float g_m1[BB*HH], g_x2[BB*HH], g_m2[BB*HH];
static __device__ __align__(16) float g_m1P [16*(size_t)BB*HH];
static __device__ __align__(16) float g_t2P [16*(size_t)BB*HH];
static __device__ __align__(16) float g_m2xP[16*(size_t)BB*HH];
static __device__ __align__(16) float g_z1P [8*(size_t)BB*Z4];
static __device__ __align__(16) float g_z2aP[8*(size_t)BB*Z4];
static __device__ __align__(16) float g_z2bP[8*(size_t)BB*Z4];
static __device__ float g_s[BB];
static __device__ float g_flagbuf[2];

static __device__ unsigned g_bar_count = 0;
static __device__ volatile unsigned g_bar_gen = 0;

__device__ __forceinline__ float sigf(float x) { return 1.0f / (1.0f + expf(-x)); }

__device__ __forceinline__ u64t dup2(float v) {
    u64t r; asm("mov.b64 %0, {%1, %1};" : "=l"(r) : "f"(v)); return r;
}
__device__ __forceinline__ void fma2(u64t& d, u64t a, u64t b) {
    asm("fma.rn.f32x2 %0, %1, %2, %0;" : "+l"(d) : "l"(a), "l"(b));
}
__device__ __forceinline__ void upk2(u64t v, float& lo, float& hi) {
    asm("mov.b64 {%0, %1}, %2;" : "=f"(lo), "=f"(hi) : "l"(v));
}

__device__ __forceinline__ void gsync(unsigned nb)
{
    __syncthreads();
    if (threadIdx.x == 0) {
        __threadfence();
        unsigned gen = g_bar_gen;
        if (atomicAdd(&g_bar_count, 1u) == nb - 1u) {
            g_bar_count = 0;
            __threadfence();
            g_bar_gen = gen + 1u;
        } else {
            while (g_bar_gen == gen) __nanosleep(64);
        }
        __threadfence();
    }
    __syncthreads();
}

// ================= unified GEMM tile: 128 rows x 64 cols, K-chunked =================
// SMEM: As 2 bufs x [16k x 132] (row-pairs read as u64);
//       Wd 2 bufs x [16k x 136] (each w stored duplicated -> 64-bit LDS == dup2).
// Per-element FMA order identical to R11's dgL (bit-identical results).
// EPI: 0 plain, 1 +bias[col], 2 +ex[C-indexed]
template<int EPI>
__device__ __noinline__ void dgL(
    const float* __restrict__ A, int lda,
    const float* __restrict__ W, int ldw,
    float* __restrict__ C, int ldc,
    int col0, int k0, int niter,
    const float* __restrict__ ex,
    float* __restrict__ As, float* __restrict__ Wd)
{
    const int tid = threadIdx.x;
    const int lmA = tid >> 1, kqA = (tid & 1) << 3;   // A tile: 128 rows x 16 k
    const int lmW = tid >> 2, kqW = (tid & 3) << 2;   // W tile: 64 rows x 16 k
    const float* Ag = A + (size_t)lmA*lda + k0 + kqA;
    const float* Wg = W + (size_t)(col0 + lmW)*ldw + k0 + kqW;
    const int m0 = (tid >> 4) << 3;   // 8 rows per thread
    const int n0 = (tid & 15) << 2;   // 4 cols per thread
    u64t acc[4][4];
    #pragma unroll
    for (int i = 0; i < 4; i++)
        #pragma unroll
        for (int j = 0; j < 4; j++) acc[i][j] = 0ull;

    float4 a0 = *(const float4*)Ag;
    float4 a1 = *(const float4*)(Ag + 4);
    float4 w0 = *(const float4*)Wg;

    for (int it = 0; it < niter; it++) {
        const int bA = (it & 1) * (16*132);
        const int bW = (it & 1) * (16*136);
        // store A (scalar: pairs land contiguously -> u64-readable)
        As[bA+(kqA+0)*132+lmA]=a0.x; As[bA+(kqA+1)*132+lmA]=a0.y;
        As[bA+(kqA+2)*132+lmA]=a0.z; As[bA+(kqA+3)*132+lmA]=a0.w;
        As[bA+(kqA+4)*132+lmA]=a1.x; As[bA+(kqA+5)*132+lmA]=a1.y;
        As[bA+(kqA+6)*132+lmA]=a1.z; As[bA+(kqA+7)*132+lmA]=a1.w;
        // store W duplicated (STS.64 of dup2)
        *(u64t*)(Wd + bW + (kqW+0)*136 + 2*lmW) = dup2(w0.x);
        *(u64t*)(Wd + bW + (kqW+1)*136 + 2*lmW) = dup2(w0.y);
        *(u64t*)(Wd + bW + (kqW+2)*136 + 2*lmW) = dup2(w0.z);
        *(u64t*)(Wd + bW + (kqW+3)*136 + 2*lmW) = dup2(w0.w);
        __syncthreads();
        if (it + 1 < niter) {
            const float* An = Ag + (it+1)*16;
            a0 = *(const float4*)An; a1 = *(const float4*)(An + 4);
            w0 = *(const float4*)(Wg + (it+1)*16);
        }
        #pragma unroll
        for (int kk = 0; kk < 16; kk++) {
            const float* ar = As + bA + kk*132 + m0;
            const float* wr = Wd + bW + kk*136 + 2*n0;
            ulonglong2 A0 = *(const ulonglong2*)ar;        // rows (m0,m0+1),(m0+2,m0+3)
            ulonglong2 A1 = *(const ulonglong2*)(ar + 4);  // rows (m0+4,..),(m0+6,..)
            ulonglong2 W0 = *(const ulonglong2*)wr;        // dup(w[n0]), dup(w[n0+1])
            ulonglong2 W1 = *(const ulonglong2*)(wr + 4);  // dup(w[n0+2]), dup(w[n0+3])
            fma2(acc[0][0], A0.x, W0.x); fma2(acc[0][1], A0.x, W0.y);
            fma2(acc[0][2], A0.x, W1.x); fma2(acc[0][3], A0.x, W1.y);
            fma2(acc[1][0], A0.y, W0.x); fma2(acc[1][1], A0.y, W0.y);
            fma2(acc[1][2], A0.y, W1.x); fma2(acc[1][3], A0.y, W1.y);
            fma2(acc[2][0], A1.x, W0.x); fma2(acc[2][1], A1.x, W0.y);
            fma2(acc[2][2], A1.x, W1.x); fma2(acc[2][3], A1.x, W1.y);
            fma2(acc[3][0], A1.y, W0.x); fma2(acc[3][1], A1.y, W0.y);
            fma2(acc[3][2], A1.y, W1.x); fma2(acc[3][3], A1.y, W1.y);
        }
        __syncthreads();
    }

    #pragma unroll
    for (int i = 0; i < 4; i++) {
        float lo[4], hi[4];
        #pragma unroll
        for (int j = 0; j < 4; j++) upk2(acc[i][j], lo[j], hi[j]);
        size_t r0 = (size_t)(m0 + 2*i) * ldc + col0 + n0;
        size_t r1 = r0 + ldc;
        float4 v = make_float4(lo[0],lo[1],lo[2],lo[3]);
        float4 u = make_float4(hi[0],hi[1],hi[2],hi[3]);
        if (EPI == 1) {
            float4 bb = *(const float4*)(ex + col0 + n0);
            v.x+=bb.x; v.y+=bb.y; v.z+=bb.z; v.w+=bb.w;
            u.x+=bb.x; u.y+=bb.y; u.z+=bb.z; u.w+=bb.w;
        } else if (EPI == 2) {
            float4 e0 = *(const float4*)(ex + r0);
            float4 e1 = *(const float4*)(ex + r1);
            v.x+=e0.x; v.y+=e0.y; v.z+=e0.z; v.w+=e0.w;
            u.x+=e1.x; u.y+=e1.y; u.z+=e1.z; u.w+=e1.w;
        }
        *(float4*)(C + r0) = v;
        *(float4*)(C + r1) = u;
    }
}

// ---------------- precompute GEMM wrapper (rows via blockIdx.y) ----------------
template<int EPI>
__global__ void __launch_bounds__(256, 2) gemmP(
    const float* __restrict__ A, int lda, const float* __restrict__ W,
    float* __restrict__ C, int N, int K, const float* __restrict__ bias)
{
    __shared__ __align__(16) float As[2*16*132];
    __shared__ __align__(16) float Wd[2*16*136];
    dgL<EPI>(A + (size_t)blockIdx.y*128*lda, lda, W, K,
             C + (size_t)blockIdx.y*128*N, N,
             blockIdx.x*64, 0, K/16, bias, As, Wd);
}

// ---------------- prep + embed (unchanged) ----------------
__global__ void k_prep(const float* __restrict__ vs, const float* __restrict__ Wsi,
                       const float* __restrict__ Wsh, const float* __restrict__ b_bd)
{
    int i = blockIdx.x;
    __shared__ float red[256];
    float acc = 0.f;
    if (i < FT) {
        for (int j = threadIdx.x; j < MD; j += 256) acc += vs[j] * Wsi[(size_t)j*FT + i];
    } else if (i < FT + HH) {
        int h = i - FT;
        for (int j = threadIdx.x; j < MD; j += 256) acc += vs[j] * Wsh[(size_t)j*HH + h];
    } else {
        for (int j = threadIdx.x; j < MD; j += 256) acc += vs[j] * b_bd[j];
    }
    red[threadIdx.x] = acc; __syncthreads();
    for (int off = 128; off; off >>= 1) {
        if (threadIdx.x < off) red[threadIdx.x] += red[threadIdx.x + off];
        __syncthreads();
    }
    if (threadIdx.x == 0) {
        if (i < FT) g_w[i] = red[0];
        else if (i < FT + HH) g_u[i - FT] = red[0];
        else g_c0[0] = red[0];
    }
}

__global__ void k_embed(const int* __restrict__ enc, const int* __restrict__ encx,
                        const float* __restrict__ wemb, const float* __restrict__ xemb)
{
    int n = blockIdx.x;
    int t = n >> 7;
    int b = n & 127;
    int w = enc [b*SL + t];
    int e = encx[b*SL + t];
    float4* dst = (float4*)(g_X + (size_t)n*FT);
    const float4* ws = (const float4*)(wemb + (size_t)w*512);
    const float4* xs = (const float4*)(xemb + (size_t)e*64);
    const float4* w4 = (const float4*)g_w;
    float dot = 0.f;
    for (int i = threadIdx.x; i < 128; i += 128) {
        float4 v = ws[i]; dst[i] = v;
        float4 c = w4[i];
        dot += v.x*c.x + v.y*c.y + v.z*c.z + v.w*c.w;
    }
    for (int i = threadIdx.x; i < 16; i += 128) {
        float4 v = xs[i]; dst[128 + i] = v;
        float4 c = w4[128 + i];
        dot += v.x*c.x + v.y*c.y + v.z*c.z + v.w*c.w;
    }
    __shared__ float red[128];
    red[threadIdx.x] = dot; __syncthreads();
    for (int off = 64; off; off >>= 1) {
        if (threadIdx.x < off) red[threadIdx.x] += red[threadIdx.x + off];
        __syncthreads();
    }
    if (threadIdx.x == 0) g_d[n] = red[0] + g_c0[0];
}

// ---------------- elementwise items (arithmetic identical to R11) ----------------
__device__ __forceinline__ float4 f4add(float4 a, float4 b) {
    return make_float4(a.x+b.x, a.y+b.y, a.z+b.z, a.w+b.w);
}

__device__ void fin_m1_b(int b, const float* __restrict__ pre_mx)
{
    const float4* P = (const float4*)g_m1P;
    int idx = b*256 + threadIdx.x;
    float4 s = make_float4(0.f,0.f,0.f,0.f);
    #pragma unroll
    for (int c = 0; c < 16; c++) s = f4add(s, P[(size_t)c*32768 + idx]);
    float4 m = ((const float4*)pre_mx)[idx];
    ((float4*)g_m1)[idx] = make_float4(s.x*m.x, s.y*m.y, s.z*m.z, s.w*m.w);
}

__device__ void fin_m2_b(int b)
{
    const float4* P = (const float4*)g_m2xP;
    const float4* T = (const float4*)g_t2P;
    int idx = b*256 + threadIdx.x;
    float4 s = make_float4(0.f,0.f,0.f,0.f);
    float4 u = make_float4(0.f,0.f,0.f,0.f);
    #pragma unroll
    for (int c = 0; c < 16; c++) {
        s = f4add(s, P[(size_t)c*32768 + idx]);
        u = f4add(u, T[(size_t)c*32768 + idx]);
    }
    ((float4*)g_m2)[idx] = make_float4(s.x*u.x, s.y*u.y, s.z*u.z, s.w*u.w);
}

__device__ void gate1_b(int b, const float* __restrict__ pre_ih)
{
    float s = g_s[b];
    int h = threadIdx.x * 4;
    const float* pz = pre_ih + (size_t)b*Z4;
    float4 zi = *(const float4*)(pz + h);
    float4 zf = *(const float4*)(pz + HH + h);
    float4 zg = *(const float4*)(pz + 2*HH + h);
    float4 zo = *(const float4*)(pz + 3*HH + h);
    #pragma unroll
    for (int c = 0; c < 8; c++) {
        const float* pp = g_z1P + (size_t)c*BB*Z4 + (size_t)b*Z4;
        zi = f4add(zi, *(const float4*)(pp + h));
        zf = f4add(zf, *(const float4*)(pp + HH + h));
        zg = f4add(zg, *(const float4*)(pp + 2*HH + h));
        zo = f4add(zo, *(const float4*)(pp + 3*HH + h));
    }
    int base = b*HH + h;
    float4 c1 = *(const float4*)(g_c1 + base);
    float4 cn, hn;
    cn.x = sigf(zf.x)*c1.x + sigf(zi.x)*tanhf(zg.x);
    cn.y = sigf(zf.y)*c1.y + sigf(zi.y)*tanhf(zg.y);
    cn.z = sigf(zf.z)*c1.z + sigf(zi.z)*tanhf(zg.z);
    cn.w = sigf(zf.w)*c1.w + sigf(zi.w)*tanhf(zg.w);
    hn.x = sigf(zo.x)*tanhf(cn.x);
    hn.y = sigf(zo.y)*tanhf(cn.y);
    hn.z = sigf(zo.z)*tanhf(cn.z);
    hn.w = sigf(zo.w)*tanhf(cn.w);
    float om = 1.f - s;
    *(float4*)(g_x2 + base) = make_float4(hn.x*s, hn.y*s, hn.z*s, hn.w*s);
    *(float4*)(g_h1 + base) = make_float4(hn.x*om, hn.y*om, hn.z*om, hn.w*om);
    *(float4*)(g_c1 + base) = make_float4(cn.x*om, cn.y*om, cn.z*om, cn.w*om);
}

__device__ void gate2out4(int t, int g, float* __restrict__ out,
                          const float* __restrict__ b2, bool fin)
{
    bool upd = g_flagbuf[t & 1] > 0.5f;
    int b0 = g*4;
    int h = threadIdx.x * 4;
    for (int b = b0; b < b0+4; b++) {
        int base = b*HH + h;
        float4 hv, cv;
        if (upd) {
            float4 zi = *(const float4*)(b2 + h);
            float4 zf = *(const float4*)(b2 + HH + h);
            float4 zg = *(const float4*)(b2 + 2*HH + h);
            float4 zo = *(const float4*)(b2 + 3*HH + h);
            #pragma unroll
            for (int c = 0; c < 8; c++) {
                const float* pp = g_z2bP + (size_t)c*BB*Z4 + (size_t)b*Z4;
                zi = f4add(zi, *(const float4*)(pp + h));
                zf = f4add(zf, *(const float4*)(pp + HH + h));
                zg = f4add(zg, *(const float4*)(pp + 2*HH + h));
                zo = f4add(zo, *(const float4*)(pp + 3*HH + h));
            }
            float4 c2 = *(const float4*)(g_c2 + base);
            cv.x = sigf(zf.x)*c2.x + sigf(zi.x)*tanhf(zg.x);
            cv.y = sigf(zf.y)*c2.y + sigf(zi.y)*tanhf(zg.y);
            cv.z = sigf(zf.z)*c2.z + sigf(zi.z)*tanhf(zg.z);
            cv.w = sigf(zf.w)*c2.w + sigf(zi.w)*tanhf(zg.w);
            hv.x = sigf(zo.x)*tanhf(cv.x);
            hv.y = sigf(zo.y)*tanhf(cv.y);
            hv.z = sigf(zo.z)*tanhf(cv.z);
            hv.w = sigf(zo.w)*tanhf(cv.w);
            *(float4*)(g_c2 + base) = cv;
            *(float4*)(g_h2 + base) = hv;
        } else {
            hv = *(const float4*)(g_h2 + base);
            cv = *(const float4*)(g_c2 + base);
        }
        *(float4*)(out + (size_t)b*SL*HH + (size_t)t*HH + h) = hv;
        if (fin) {
            size_t off = (size_t)BB*SL*HH;
            *(float4*)(out + off + base) = hv;
            *(float4*)(out + off + (size_t)BB*HH + base) = cv;
        }
    }
}

__device__ void sdot16(int t, int k, float* __restrict__ out)
{
    int warp = threadIdx.x >> 5, lane = threadIdx.x & 31;
    int base = k*16 + warp*2;
    for (int bi = 0; bi < 2; bi++) {
        int b = base + bi;
        const float* hp = g_h1 + (size_t)b*HH;
        float p = 0.f;
        for (int j = lane; j < HH; j += 32) p += hp[j] * g_u[j];
        #pragma unroll
        for (int o = 16; o; o >>= 1) p += __shfl_xor_sync(0xffffffffu, p, o);
        if (lane == 0) {
            float sv = (p + g_d[(size_t)t*BB + b] > 0.f) ? 1.f : 0.f;
            g_s[b] = sv;
            if (b == 0) {
                g_flagbuf[t & 1] = sv;
                out[(size_t)BB*SL*HH + 2*(size_t)BB*HH + t] = sv;
            }
        }
    }
}

// ---------------- persistent recurrent-loop kernel (2 CTAs/SM) ----------------
__global__ void __launch_bounds__(256, 2) k_loop(
    const float* __restrict__ Wmh1, const float* __restrict__ Whh1,
    const float* __restrict__ Wmx2, const float* __restrict__ Wmh2,
    const float* __restrict__ Wih2, const float* __restrict__ Whh2,
    const float* __restrict__ b2, float* __restrict__ out)
{
    __shared__ __align__(16) float As[2*16*132];
    __shared__ __align__(16) float Wd[2*16*136];
    const int bid = blockIdx.x;
    const unsigned G = gridDim.x;

    for (int t = 0; t < SL; t++) {
        const float* pre_mx = g_pmx + (size_t)t*BB*HH;
        const float* pre_ih = g_pih + (size_t)t*BB*Z4;

        // Phase A (296 items == G): m1 partials (256) | gate2out(t-1) (32) | sdot (8)
        for (int it = bid; it < 296; it += G) {
            if (it < 256) {
                int nt = it >> 4, kc = it & 15;
                dgL<0>(g_h1, HH, Wmh1, HH, g_m1P + (size_t)kc*BB*HH, HH,
                       nt*64, kc*64, 4, nullptr, As, Wd);
            } else if (it < 288) {
                if (t > 0) gate2out4(t-1, it-256, out, b2, false);
            } else
                sdot16(t, it-288, out);
        }
        gsync(G);

        // Phase A2: m1 = pre_mx * sum(partials)  (128 items)
        for (int it = bid; it < 128; it += G) fin_m1_b(it, pre_mx);
        gsync(G);

        float flag = g_flagbuf[t & 1];
        int nB = (flag > 0.5f) ? 768 : 512;

        // Phase B: z1 partials (512) | t2 partials (256, flag)
        for (int it = bid; it < nB; it += G) {
            if (it < 512) {
                int nt = it >> 3, kc = it & 7;
                dgL<0>(g_m1, HH, Whh1, HH, g_z1P + (size_t)kc*BB*Z4, Z4,
                       nt*64, kc*128, 8, nullptr, As, Wd);
            } else {
                int j = it - 512, nt = j >> 4, kc = j & 15;
                dgL<0>(g_h2, HH, Wmh2, HH, g_t2P + (size_t)kc*BB*HH, HH,
                       nt*64, kc*64, 4, nullptr, As, Wd);
            }
        }
        gsync(G);

        // Phase C: gate1 (128 items)
        for (int it = bid; it < 128; it += G) gate1_b(it, pre_ih);
        gsync(G);

        if (flag > 0.5f) {
            // Phase D: z2a partials (512) | m2x partials (256)
            for (int it = bid; it < 768; it += G) {
                if (it < 512) {
                    int nt = it >> 3, kc = it & 7;
                    dgL<0>(g_x2, HH, Wih2, HH, g_z2aP + (size_t)kc*BB*Z4, Z4,
                           nt*64, kc*128, 8, nullptr, As, Wd);
                } else {
                    int j = it - 512, nt = j >> 4, kc = j & 15;
                    dgL<0>(g_x2, HH, Wmx2, HH, g_m2xP + (size_t)kc*BB*HH, HH,
                           nt*64, kc*64, 4, nullptr, As, Wd);
                }
            }
            gsync(G);
            // Phase D2: m2 = sum(m2xP) * sum(t2P)  (128 items)
            for (int it = bid; it < 128; it += G) fin_m2_b(it);
            gsync(G);
            // Phase E: z2bP[kc] = m2@Whh2^T partial + z2aP[kc]  (512 items)
            for (int it = bid; it < 512; it += G) {
                int nt = it >> 3, kc = it & 7;
                dgL<2>(g_m2, HH, Whh2, HH, g_z2bP + (size_t)kc*BB*Z4, Z4,
                       nt*64, kc*128, 8, g_z2aP + (size_t)kc*BB*Z4, As, Wd);
            }
            gsync(G);
        }
    }

    // final step outputs + final states
    for (int it = bid; it < 32; it += (int)G)
        gate2out4(SL-1, it, out, b2, true);
}

// ---------------- host ----------------
extern "C" void kernel_launch(void* const* d_in, const int* in_sizes, int n_in,
                              void* d_out, int out_size)
{
    const int*   enc  = (const int*)  d_in[0];
    const int*   encx = (const int*)  d_in[1];
    const float* wemb = (const float*)d_in[2];
    const float* xemb = (const float*)d_in[3];
    const float* Wsi  = (const float*)d_in[4];
    const float* Wsh  = (const float*)d_in[5];
    const float* b_bd = (const float*)d_in[6];
    const float* vs   = (const float*)d_in[7];
    const float* Wmx1 = (const float*)d_in[8];
    const float* Wmh1 = (const float*)d_in[9];
    const float* Wih1 = (const float*)d_in[10];
    const float* Whh1 = (const float*)d_in[11];
    const float* b1   = (const float*)d_in[12];
    const float* Wmx2 = (const float*)d_in[13];
    const float* Wmh2 = (const float*)d_in[14];
    const float* Wih2 = (const float*)d_in[15];
    const float* Whh2 = (const float*)d_in[16];
    const float* b2   = (const float*)d_in[17];
    float* out = (float*)d_out;

    float *pX, *pmx, *pih, *ph1, *pc1, *ph2, *pc2;
    cudaGetSymbolAddress((void**)&pX,  g_X);
    cudaGetSymbolAddress((void**)&pmx, g_pmx);
    cudaGetSymbolAddress((void**)&pih, g_pih);
    cudaGetSymbolAddress((void**)&ph1, g_h1);
    cudaGetSymbolAddress((void**)&pc1, g_c1);
    cudaGetSymbolAddress((void**)&ph2, g_h2);
    cudaGetSymbolAddress((void**)&pc2, g_c2);

    cudaMemsetAsync(ph1, 0, (size_t)BB*HH*sizeof(float));
    cudaMemsetAsync(pc1, 0, (size_t)BB*HH*sizeof(float));
    cudaMemsetAsync(ph2, 0, (size_t)BB*HH*sizeof(float));
    cudaMemsetAsync(pc2, 0, (size_t)BB*HH*sizeof(float));

    // precompute
    k_prep<<<FT + HH + 1, 256>>>(vs, Wsi, Wsh, b_bd);
    k_embed<<<NT, 128>>>(enc, encx, wemb, xemb);
    gemmP<0><<<dim3(HH/64, NT/128), 256>>>(pX, FT, Wmx1, pmx, HH, FT, nullptr);
    gemmP<1><<<dim3(Z4/64, NT/128), 256>>>(pX, FT, Wih1, pih, Z4, FT, b1);

    // recurrent loop: one persistent kernel, 2 CTAs/SM
    k_loop<<<G2, 256>>>(Wmh1, Whh1, Wmx2, Wmh2, Wih2, Whh2, b2, out);
}

// round 14
// speedup vs baseline: 1.6767x; 1.6767x over previous
#include <cuda_runtime.h>
#include <math.h>

#define SL 512
#define BB 128
#define HH 1024
#define FT 576
#define MD 512
#define Z4 4096
#define NT (SL*BB)
#define G2 296        // persistent grid: 2 CTAs/SM x 148 SMs (launch_bounds(256,2))

typedef unsigned long long u64t;

// ---------------- static device scratch ----------------
static __device__ __align__(16) float g_X  [(size_t)NT*FT];
static __device__ __align__(16) float g_pmx[(size_t)NT*HH];   // X@Wmx1^T
static __device__ __align__(16) float g_pih[(size_t)NT*Z4];   // X@Wih1^T + b1
static __device__ __align__(16) float g_d  [(size_t)NT];      // (X@Wsi^T+b_bd)·vs
static __device__ __align__(16) float g_w  [FT];
static __device__ __align__(16) float g_u  [HH];
static __device__ float g_c0[1];
static __device__ __align__(16) float g_h1[BB*HH], g_c1[BB*HH], g_h2[BB*HH], g_c2[BB*HH];
static __device__ __align__(16) float g_m1[BB*HH], g_x2[BB*HH], g_m2[BB*HH];
static __device__ __align__(16) float g_m1P [16*(size_t)BB*HH];
static __device__ __align__(16) float g_t2P [16*(size_t)BB*HH];
static __device__ __align__(16) float g_m2xP[16*(size_t)BB*HH];
static __device__ __align__(16) float g_z1P [8*(size_t)BB*Z4];
static __device__ __align__(16) float g_z2aP[8*(size_t)BB*Z4];
static __device__ __align__(16) float g_z2bP[8*(size_t)BB*Z4];
static __device__ float g_s[BB];
static __device__ float g_flagbuf[2];

static __device__ unsigned g_bar_count = 0;
static __device__ volatile unsigned g_bar_gen = 0;

__device__ __forceinline__ float sigf(float x) { return 1.0f / (1.0f + expf(-x)); }

__device__ __forceinline__ u64t dup2(float v) {
    u64t r; asm("mov.b64 %0, {%1, %1};" : "=l"(r) : "f"(v)); return r;
}
__device__ __forceinline__ void fma2(u64t& d, u64t a, u64t b) {
    asm("fma.rn.f32x2 %0, %1, %2, %0;" : "+l"(d) : "l"(a), "l"(b));
}
__device__ __forceinline__ void upk2(u64t v, float& lo, float& hi) {
    asm("mov.b64 {%0, %1}, %2;" : "=f"(lo), "=f"(hi) : "l"(v));
}

__device__ __forceinline__ void gsync(unsigned nb)
{
    __syncthreads();
    if (threadIdx.x == 0) {
        __threadfence();
        unsigned gen = g_bar_gen;
        if (atomicAdd(&g_bar_count, 1u) == nb - 1u) {
            g_bar_count = 0;
            __threadfence();
            g_bar_gen = gen + 1u;
        } else {
            while (g_bar_gen == gen) __nanosleep(64);
        }
        __threadfence();
    }
    __syncthreads();
}

// ================= unified GEMM tile: 128 rows x 64 cols, K-chunked =================
// Hybrid layout:
//   As: 2 bufs x [16k x 132] scalar rows -> row-PAIRS read directly as u64 (no pack movs)
//   Ws: 2 bufs x [16k x 68]  plain floats -> float4 LDS + dup2 movs (R11 byte traffic)
// Double-buffered: ONE __syncthreads per K-iter (+1 entry sync guarding buffer reuse).
// Per-element FMA order bit-identical to R11/R12.
// EPI: 0 plain, 1 +bias[col], 2 +ex[C-indexed]
template<int EPI>
__device__ __noinline__ void dgL(
    const float* __restrict__ A, int lda,
    const float* __restrict__ W, int ldw,
    float* __restrict__ C, int ldc,
    int col0, int k0, int niter,
    const float* __restrict__ ex,
    float* __restrict__ As, float* __restrict__ Ws)
{
    const int tid = threadIdx.x;
    const int lmA = tid >> 1, kqA = (tid & 1) << 3;   // A tile: 128 rows x 16 k
    const int lmW = tid >> 2, kqW = (tid & 3) << 2;   // W tile: 64 rows x 16 k
    const float* Ag = A + (size_t)lmA*lda + k0 + kqA;
    const float* Wg = W + (size_t)(col0 + lmW)*ldw + k0 + kqW;
    const int m0 = (tid >> 4) << 3;   // 8 rows per thread
    const int n0 = (tid & 15) << 2;   // 4 cols per thread
    u64t acc[4][4];
    #pragma unroll
    for (int i = 0; i < 4; i++)
        #pragma unroll
        for (int j = 0; j < 4; j++) acc[i][j] = 0ull;

    float4 a0 = *(const float4*)Ag;
    float4 a1 = *(const float4*)(Ag + 4);
    float4 w0 = *(const float4*)Wg;

    __syncthreads();   // guard: prior dgL reads of buffer 0 must complete before store below

    for (int it = 0; it < niter; it++) {
        const int bA = (it & 1) * (16*132);
        const int bW = (it & 1) * (16*68);
        // store A (scalar: row-pairs land contiguously -> u64-readable)
        As[bA+(kqA+0)*132+lmA]=a0.x; As[bA+(kqA+1)*132+lmA]=a0.y;
        As[bA+(kqA+2)*132+lmA]=a0.z; As[bA+(kqA+3)*132+lmA]=a0.w;
        As[bA+(kqA+4)*132+lmA]=a1.x; As[bA+(kqA+5)*132+lmA]=a1.y;
        As[bA+(kqA+6)*132+lmA]=a1.z; As[bA+(kqA+7)*132+lmA]=a1.w;
        // store W plain (R11 layout -> 16B LDS reads)
        Ws[bW+(kqW+0)*68+lmW]=w0.x; Ws[bW+(kqW+1)*68+lmW]=w0.y;
        Ws[bW+(kqW+2)*68+lmW]=w0.z; Ws[bW+(kqW+3)*68+lmW]=w0.w;
        __syncthreads();
        if (it + 1 < niter) {
            const float* An = Ag + (it+1)*16;
            a0 = *(const float4*)An; a1 = *(const float4*)(An + 4);
            w0 = *(const float4*)(Wg + (it+1)*16);
        }
        #pragma unroll
        for (int kk = 0; kk < 16; kk++) {
            const float* ar = As + bA + kk*132 + m0;
            ulonglong2 A0 = *(const ulonglong2*)ar;        // rows (m0,m0+1),(m0+2,m0+3)
            ulonglong2 A1 = *(const ulonglong2*)(ar + 4);  // rows (m0+4,m0+5),(m0+6,m0+7)
            float4 xw = *(const float4*)(Ws + bW + kk*68 + n0);
            u64t W0 = dup2(xw.x), W1 = dup2(xw.y), W2 = dup2(xw.z), W3 = dup2(xw.w);
            fma2(acc[0][0], A0.x, W0); fma2(acc[0][1], A0.x, W1);
            fma2(acc[0][2], A0.x, W2); fma2(acc[0][3], A0.x, W3);
            fma2(acc[1][0], A0.y, W0); fma2(acc[1][1], A0.y, W1);
            fma2(acc[1][2], A0.y, W2); fma2(acc[1][3], A0.y, W3);
            fma2(acc[2][0], A1.x, W0); fma2(acc[2][1], A1.x, W1);
            fma2(acc[2][2], A1.x, W2); fma2(acc[2][3], A1.x, W3);
            fma2(acc[3][0], A1.y, W0); fma2(acc[3][1], A1.y, W1);
            fma2(acc[3][2], A1.y, W2); fma2(acc[3][3], A1.y, W3);
        }
        // no trailing sync: next iter stores to the OTHER buffer; reuse of this
        // buffer two iters later is ordered by the next iter's sync.
    }

    #pragma unroll
    for (int i = 0; i < 4; i++) {
        float lo[4], hi[4];
        #pragma unroll
        for (int j = 0; j < 4; j++) upk2(acc[i][j], lo[j], hi[j]);
        size_t r0 = (size_t)(m0 + 2*i) * ldc + col0 + n0;
        size_t r1 = r0 + ldc;
        float4 v = make_float4(lo[0],lo[1],lo[2],lo[3]);
        float4 u = make_float4(hi[0],hi[1],hi[2],hi[3]);
        if (EPI == 1) {
            float4 bb = *(const float4*)(ex + col0 + n0);
            v.x+=bb.x; v.y+=bb.y; v.z+=bb.z; v.w+=bb.w;
            u.x+=bb.x; u.y+=bb.y; u.z+=bb.z; u.w+=bb.w;
        } else if (EPI == 2) {
            float4 e0 = *(const float4*)(ex + r0);
            float4 e1 = *(const float4*)(ex + r1);
            v.x+=e0.x; v.y+=e0.y; v.z+=e0.z; v.w+=e0.w;
            u.x+=e1.x; u.y+=e1.y; u.z+=e1.z; u.w+=e1.w;
        }
        *(float4*)(C + r0) = v;
        *(float4*)(C + r1) = u;
    }
}

// ---------------- precompute GEMM wrapper (rows via blockIdx.y) ----------------
template<int EPI>
__global__ void __launch_bounds__(256, 2) gemmP(
    const float* __restrict__ A, int lda, const float* __restrict__ W,
    float* __restrict__ C, int N, int K, const float* __restrict__ bias)
{
    __shared__ __align__(16) float As[2*16*132];
    __shared__ __align__(16) float Ws[2*16*68];
    dgL<EPI>(A + (size_t)blockIdx.y*128*lda, lda, W, K,
             C + (size_t)blockIdx.y*128*N, N,
             blockIdx.x*64, 0, K/16, bias, As, Ws);
}

// ---------------- prep + embed (unchanged) ----------------
__global__ void k_prep(const float* __restrict__ vs, const float* __restrict__ Wsi,
                       const float* __restrict__ Wsh, const float* __restrict__ b_bd)
{
    int i = blockIdx.x;
    __shared__ float red[256];
    float acc = 0.f;
    if (i < FT) {
        for (int j = threadIdx.x; j < MD; j += 256) acc += vs[j] * Wsi[(size_t)j*FT + i];
    } else if (i < FT + HH) {
        int h = i - FT;
        for (int j = threadIdx.x; j < MD; j += 256) acc += vs[j] * Wsh[(size_t)j*HH + h];
    } else {
        for (int j = threadIdx.x; j < MD; j += 256) acc += vs[j] * b_bd[j];
    }
    red[threadIdx.x] = acc; __syncthreads();
    for (int off = 128; off; off >>= 1) {
        if (threadIdx.x < off) red[threadIdx.x] += red[threadIdx.x + off];
        __syncthreads();
    }
    if (threadIdx.x == 0) {
        if (i < FT) g_w[i] = red[0];
        else if (i < FT + HH) g_u[i - FT] = red[0];
        else g_c0[0] = red[0];
    }
}

__global__ void k_embed(const int* __restrict__ enc, const int* __restrict__ encx,
                        const float* __restrict__ wemb, const float* __restrict__ xemb)
{
    int n = blockIdx.x;
    int t = n >> 7;
    int b = n & 127;
    int w = enc [b*SL + t];
    int e = encx[b*SL + t];
    float4* dst = (float4*)(g_X + (size_t)n*FT);
    const float4* ws = (const float4*)(wemb + (size_t)w*512);
    const float4* xs = (const float4*)(xemb + (size_t)e*64);
    const float4* w4 = (const float4*)g_w;
    float dot = 0.f;
    for (int i = threadIdx.x; i < 128; i += 128) {
        float4 v = ws[i]; dst[i] = v;
        float4 c = w4[i];
        dot += v.x*c.x + v.y*c.y + v.z*c.z + v.w*c.w;
    }
    for (int i = threadIdx.x; i < 16; i += 128) {
        float4 v = xs[i]; dst[128 + i] = v;
        float4 c = w4[128 + i];
        dot += v.x*c.x + v.y*c.y + v.z*c.z + v.w*c.w;
    }
    __shared__ float red[128];
    red[threadIdx.x] = dot; __syncthreads();
    for (int off = 64; off; off >>= 1) {
        if (threadIdx.x < off) red[threadIdx.x] += red[threadIdx.x + off];
        __syncthreads();
    }
    if (threadIdx.x == 0) g_d[n] = red[0] + g_c0[0];
}

// ---------------- elementwise items (arithmetic identical to R11) ----------------
__device__ __forceinline__ float4 f4add(float4 a, float4 b) {
    return make_float4(a.x+b.x, a.y+b.y, a.z+b.z, a.w+b.w);
}

__device__ void fin_m1_b(int b, const float* __restrict__ pre_mx)
{
    const float4* P = (const float4*)g_m1P;
    int idx = b*256 + threadIdx.x;
    float4 s = make_float4(0.f,0.f,0.f,0.f);
    #pragma unroll
    for (int c = 0; c < 16; c++) s = f4add(s, P[(size_t)c*32768 + idx]);
    float4 m = ((const float4*)pre_mx)[idx];
    ((float4*)g_m1)[idx] = make_float4(s.x*m.x, s.y*m.y, s.z*m.z, s.w*m.w);
}

__device__ void fin_m2_b(int b)
{
    const float4* P = (const float4*)g_m2xP;
    const float4* T = (const float4*)g_t2P;
    int idx = b*256 + threadIdx.x;
    float4 s = make_float4(0.f,0.f,0.f,0.f);
    float4 u = make_float4(0.f,0.f,0.f,0.f);
    #pragma unroll
    for (int c = 0; c < 16; c++) {
        s = f4add(s, P[(size_t)c*32768 + idx]);
        u = f4add(u, T[(size_t)c*32768 + idx]);
    }
    ((float4*)g_m2)[idx] = make_float4(s.x*u.x, s.y*u.y, s.z*u.z, s.w*u.w);
}

__device__ void gate1_b(int b, const float* __restrict__ pre_ih)
{
    float s = g_s[b];
    int h = threadIdx.x * 4;
    const float* pz = pre_ih + (size_t)b*Z4;
    float4 zi = *(const float4*)(pz + h);
    float4 zf = *(const float4*)(pz + HH + h);
    float4 zg = *(const float4*)(pz + 2*HH + h);
    float4 zo = *(const float4*)(pz + 3*HH + h);
    #pragma unroll
    for (int c = 0; c < 8; c++) {
        const float* pp = g_z1P + (size_t)c*BB*Z4 + (size_t)b*Z4;
        zi = f4add(zi, *(const float4*)(pp + h));
        zf = f4add(zf, *(const float4*)(pp + HH + h));
        zg = f4add(zg, *(const float4*)(pp + 2*HH + h));
        zo = f4add(zo, *(const float4*)(pp + 3*HH + h));
    }
    int base = b*HH + h;
    float4 c1 = *(const float4*)(g_c1 + base);
    float4 cn, hn;
    cn.x = sigf(zf.x)*c1.x + sigf(zi.x)*tanhf(zg.x);
    cn.y = sigf(zf.y)*c1.y + sigf(zi.y)*tanhf(zg.y);
    cn.z = sigf(zf.z)*c1.z + sigf(zi.z)*tanhf(zg.z);
    cn.w = sigf(zf.w)*c1.w + sigf(zi.w)*tanhf(zg.w);
    hn.x = sigf(zo.x)*tanhf(cn.x);
    hn.y = sigf(zo.y)*tanhf(cn.y);
    hn.z = sigf(zo.z)*tanhf(cn.z);
    hn.w = sigf(zo.w)*tanhf(cn.w);
    float om = 1.f - s;
    *(float4*)(g_x2 + base) = make_float4(hn.x*s, hn.y*s, hn.z*s, hn.w*s);
    *(float4*)(g_h1 + base) = make_float4(hn.x*om, hn.y*om, hn.z*om, hn.w*om);
    *(float4*)(g_c1 + base) = make_float4(cn.x*om, cn.y*om, cn.z*om, cn.w*om);
}

__device__ void gate2out4(int t, int g, float* __restrict__ out,
                          const float* __restrict__ b2, bool fin)
{
    bool upd = g_flagbuf[t & 1] > 0.5f;
    int b0 = g*4;
    int h = threadIdx.x * 4;
    for (int b = b0; b < b0+4; b++) {
        int base = b*HH + h;
        float4 hv, cv;
        if (upd) {
            float4 zi = *(const float4*)(b2 + h);
            float4 zf = *(const float4*)(b2 + HH + h);
            float4 zg = *(const float4*)(b2 + 2*HH + h);
            float4 zo = *(const float4*)(b2 + 3*HH + h);
            #pragma unroll
            for (int c = 0; c < 8; c++) {
                const float* pp = g_z2bP + (size_t)c*BB*Z4 + (size_t)b*Z4;
                zi = f4add(zi, *(const float4*)(pp + h));
                zf = f4add(zf, *(const float4*)(pp + HH + h));
                zg = f4add(zg, *(const float4*)(pp + 2*HH + h));
                zo = f4add(zo, *(const float4*)(pp + 3*HH + h));
            }
            float4 c2 = *(const float4*)(g_c2 + base);
            cv.x = sigf(zf.x)*c2.x + sigf(zi.x)*tanhf(zg.x);
            cv.y = sigf(zf.y)*c2.y + sigf(zi.y)*tanhf(zg.y);
            cv.z = sigf(zf.z)*c2.z + sigf(zi.z)*tanhf(zg.z);
            cv.w = sigf(zf.w)*c2.w + sigf(zi.w)*tanhf(zg.w);
            hv.x = sigf(zo.x)*tanhf(cv.x);
            hv.y = sigf(zo.y)*tanhf(cv.y);
            hv.z = sigf(zo.z)*tanhf(cv.z);
            hv.w = sigf(zo.w)*tanhf(cv.w);
            *(float4*)(g_c2 + base) = cv;
            *(float4*)(g_h2 + base) = hv;
        } else {
            hv = *(const float4*)(g_h2 + base);
            cv = *(const float4*)(g_c2 + base);
        }
        *(float4*)(out + (size_t)b*SL*HH + (size_t)t*HH + h) = hv;
        if (fin) {
            size_t off = (size_t)BB*SL*HH;
            *(float4*)(out + off + base) = hv;
            *(float4*)(out + off + (size_t)BB*HH + base) = cv;
        }
    }
}

__device__ void sdot16(int t, int k, float* __restrict__ out)
{
    int warp = threadIdx.x >> 5, lane = threadIdx.x & 31;
    int base = k*16 + warp*2;
    for (int bi = 0; bi < 2; bi++) {
        int b = base + bi;
        const float* hp = g_h1 + (size_t)b*HH;
        float p = 0.f;
        for (int j = lane; j < HH; j += 32) p += hp[j] * g_u[j];
        #pragma unroll
        for (int o = 16; o; o >>= 1) p += __shfl_xor_sync(0xffffffffu, p, o);
        if (lane == 0) {
            float sv = (p + g_d[(size_t)t*BB + b] > 0.f) ? 1.f : 0.f;
            g_s[b] = sv;
            if (b == 0) {
                g_flagbuf[t & 1] = sv;
                out[(size_t)BB*SL*HH + 2*(size_t)BB*HH + t] = sv;
            }
        }
    }
}

// ---------------- persistent recurrent-loop kernel (2 CTAs/SM) ----------------
__global__ void __launch_bounds__(256, 2) k_loop(
    const float* __restrict__ Wmh1, const float* __restrict__ Whh1,
    const float* __restrict__ Wmx2, const float* __restrict__ Wmh2,
    const float* __restrict__ Wih2, const float* __restrict__ Whh2,
    const float* __restrict__ b2, float* __restrict__ out)
{
    __shared__ __align__(16) float As[2*16*132];
    __shared__ __align__(16) float Ws[2*16*68];
    const int bid = blockIdx.x;
    const unsigned G = gridDim.x;

    for (int t = 0; t < SL; t++) {
        const float* pre_mx = g_pmx + (size_t)t*BB*HH;
        const float* pre_ih = g_pih + (size_t)t*BB*Z4;

        // Phase A (296 items == G): m1 partials (256) | gate2out(t-1) (32) | sdot (8)
        for (int it = bid; it < 296; it += G) {
            if (it < 256) {
                int nt = it >> 4, kc = it & 15;
                dgL<0>(g_h1, HH, Wmh1, HH, g_m1P + (size_t)kc*BB*HH, HH,
                       nt*64, kc*64, 4, nullptr, As, Ws);
            } else if (it < 288) {
                if (t > 0) gate2out4(t-1, it-256, out, b2, false);
            } else
                sdot16(t, it-288, out);
        }
        gsync(G);

        // Phase A2: m1 = pre_mx * sum(partials)  (128 items)
        for (int it = bid; it < 128; it += G) fin_m1_b(it, pre_mx);
        gsync(G);

        float flag = g_flagbuf[t & 1];
        int nB = (flag > 0.5f) ? 768 : 512;

        // Phase B: z1 partials (512) | t2 partials (256, flag)
        for (int it = bid; it < nB; it += G) {
            if (it < 512) {
                int nt = it >> 3, kc = it & 7;
                dgL<0>(g_m1, HH, Whh1, HH, g_z1P + (size_t)kc*BB*Z4, Z4,
                       nt*64, kc*128, 8, nullptr, As, Ws);
            } else {
                int j = it - 512, nt = j >> 4, kc = j & 15;
                dgL<0>(g_h2, HH, Wmh2, HH, g_t2P + (size_t)kc*BB*HH, HH,
                       nt*64, kc*64, 4, nullptr, As, Ws);
            }
        }
        gsync(G);

        // Phase C: gate1 (128 items)
        for (int it = bid; it < 128; it += G) gate1_b(it, pre_ih);
        gsync(G);

        if (flag > 0.5f) {
            // Phase D: z2a partials (512) | m2x partials (256)
            for (int it = bid; it < 768; it += G) {
                if (it < 512) {
                    int nt = it >> 3, kc = it & 7;
                    dgL<0>(g_x2, HH, Wih2, HH, g_z2aP + (size_t)kc*BB*Z4, Z4,
                           nt*64, kc*128, 8, nullptr, As, Ws);
                } else {
                    int j = it - 512, nt = j >> 4, kc = j & 15;
                    dgL<0>(g_x2, HH, Wmx2, HH, g_m2xP + (size_t)kc*BB*HH, HH,
                           nt*64, kc*64, 4, nullptr, As, Ws);
                }
            }
            gsync(G);
            // Phase D2: m2 = sum(m2xP) * sum(t2P)  (128 items)
            for (int it = bid; it < 128; it += G) fin_m2_b(it);
            gsync(G);
            // Phase E: z2bP[kc] = m2@Whh2^T partial + z2aP[kc]  (512 items)
            for (int it = bid; it < 512; it += G) {
                int nt = it >> 3, kc = it & 7;
                dgL<2>(g_m2, HH, Whh2, HH, g_z2bP + (size_t)kc*BB*Z4, Z4,
                       nt*64, kc*128, 8, g_z2aP + (size_t)kc*BB*Z4, As, Ws);
            }
            gsync(G);
        }
    }

    // final step outputs + final states
    for (int it = bid; it < 32; it += (int)G)
        gate2out4(SL-1, it, out, b2, true);
}

// ---------------- host ----------------
extern "C" void kernel_launch(void* const* d_in, const int* in_sizes, int n_in,
                              void* d_out, int out_size)
{
    const int*   enc  = (const int*)  d_in[0];
    const int*   encx = (const int*)  d_in[1];
    const float* wemb = (const float*)d_in[2];
    const float* xemb = (const float*)d_in[3];
    const float* Wsi  = (const float*)d_in[4];
    const float* Wsh  = (const float*)d_in[5];
    const float* b_bd = (const float*)d_in[6];
    const float* vs   = (const float*)d_in[7];
    const float* Wmx1 = (const float*)d_in[8];
    const float* Wmh1 = (const float*)d_in[9];
    const float* Wih1 = (const float*)d_in[10];
    const float* Whh1 = (const float*)d_in[11];
    const float* b1   = (const float*)d_in[12];
    const float* Wmx2 = (const float*)d_in[13];
    const float* Wmh2 = (const float*)d_in[14];
    const float* Wih2 = (const float*)d_in[15];
    const float* Whh2 = (const float*)d_in[16];
    const float* b2   = (const float*)d_in[17];
    float* out = (float*)d_out;

    float *pX, *pmx, *pih, *ph1, *pc1, *ph2, *pc2;
    cudaGetSymbolAddress((void**)&pX,  g_X);
    cudaGetSymbolAddress((void**)&pmx, g_pmx);
    cudaGetSymbolAddress((void**)&pih, g_pih);
    cudaGetSymbolAddress((void**)&ph1, g_h1);
    cudaGetSymbolAddress((void**)&pc1, g_c1);
    cudaGetSymbolAddress((void**)&ph2, g_h2);
    cudaGetSymbolAddress((void**)&pc2, g_c2);

    cudaMemsetAsync(ph1, 0, (size_t)BB*HH*sizeof(float));
    cudaMemsetAsync(pc1, 0, (size_t)BB*HH*sizeof(float));
    cudaMemsetAsync(ph2, 0, (size_t)BB*HH*sizeof(float));
    cudaMemsetAsync(pc2, 0, (size_t)BB*HH*sizeof(float));

    // precompute
    k_prep<<<FT + HH + 1, 256>>>(vs, Wsi, Wsh, b_bd);
    k_embed<<<NT, 128>>>(enc, encx, wemb, xemb);
    gemmP<0><<<dim3(HH/64, NT/128), 256>>>(pX, FT, Wmx1, pmx, HH, FT, nullptr);
    gemmP<1><<<dim3(Z4/64, NT/128), 256>>>(pX, FT, Wih1, pih, Z4, FT, b1);

    // recurrent loop: one persistent kernel, 2 CTAs/SM
    k_loop<<<G2, 256>>>(Wmh1, Whh1, Wmx2, Wmh2, Wih2, Whh2, b2, out);
}

// round 16
// speedup vs baseline: 1.9468x; 1.1611x over previous
#include <cuda_runtime.h>
#include <math.h>

#define SL 512
#define BB 128
#define HH 1024
#define FT 576
#define MD 512
#define Z4 4096
#define NT (SL*BB)
#define G2 296        // persistent grid: 2 CTAs/SM x 148 SMs (launch_bounds(256,2))

typedef unsigned long long u64t;

// ---------------- static device scratch ----------------
static __device__ __align__(16) float g_X  [(size_t)NT*FT];
static __device__ __align__(16) float g_pmx[(size_t)NT*HH];   // X@Wmx1^T
static __device__ __align__(16) float g_pih[(size_t)NT*Z4];   // X@Wih1^T + b1
static __device__ __align__(16) float g_d  [(size_t)NT];      // (X@Wsi^T+b_bd)·vs
static __device__ __align__(16) float g_w  [FT];
static __device__ __align__(16) float g_u  [HH];
static __device__ float g_c0[1];
static __device__ __align__(16) float g_h1[BB*HH], g_c1[BB*HH], g_h2[BB*HH], g_c2[BB*HH];
static __device__ __align__(16) float g_m1[BB*HH], g_x2[BB*HH], g_m2[BB*HH];
static __device__ __align__(16) float g_m1P [16*(size_t)BB*HH];
static __device__ __align__(16) float g_t2P [16*(size_t)BB*HH];
static __device__ __align__(16) float g_m2xP[16*(size_t)BB*HH];
static __device__ __align__(16) float g_z1P [8*(size_t)BB*Z4];
static __device__ __align__(16) float g_z2aP[8*(size_t)BB*Z4];
static __device__ __align__(16) float g_z2bP[8*(size_t)BB*Z4];
static __device__ float g_s[BB];
static __device__ float g_flagbuf[2];

// active-row compaction state (double-buffered by step parity)
static __device__ int g_iden[BB];
static __device__ int g_act1[2][BB], g_act2[2][BB];
static __device__ int g_pos1[2][BB], g_pos2[2][BB];
static __device__ int g_n1[2], g_n2[2];

static __device__ unsigned g_bar_count = 0;
static __device__ volatile unsigned g_bar_gen = 0;

__device__ __forceinline__ float sigf(float x) { return 1.0f / (1.0f + expf(-x)); }

__device__ __forceinline__ u64t dup2(float v) {
    u64t r; asm("mov.b64 %0, {%1, %1};" : "=l"(r) : "f"(v)); return r;
}
__device__ __forceinline__ void fma2(u64t& d, u64t a, u64t b) {
    asm("fma.rn.f32x2 %0, %1, %2, %0;" : "+l"(d) : "l"(a), "l"(b));
}
__device__ __forceinline__ void upk2(u64t v, float& lo, float& hi) {
    asm("mov.b64 {%0, %1}, %2;" : "=f"(lo), "=f"(hi) : "l"(v));
}

__device__ __forceinline__ void gsync(unsigned nb)
{
    __syncthreads();
    if (threadIdx.x == 0) {
        __threadfence();
        unsigned gen = g_bar_gen;
        if (atomicAdd(&g_bar_count, 1u) == nb - 1u) {
            g_bar_count = 0;
            __threadfence();
            g_bar_gen = gen + 1u;
        } else {
            while (g_bar_gen == gen) __nanosleep(64);
        }
        __threadfence();
    }
    __syncthreads();
}

// ================= precompute GEMM tile (R14 dgL, unchanged) =================
template<int EPI>
__device__ __noinline__ void dgL(
    const float* __restrict__ A, int lda,
    const float* __restrict__ W, int ldw,
    float* __restrict__ C, int ldc,
    int col0, int k0, int niter,
    const float* __restrict__ ex,
    float* __restrict__ As, float* __restrict__ Ws)
{
    const int tid = threadIdx.x;
    const int lmA = tid >> 1, kqA = (tid & 1) << 3;
    const int lmW = tid >> 2, kqW = (tid & 3) << 2;
    const float* Ag = A + (size_t)lmA*lda + k0 + kqA;
    const float* Wg = W + (size_t)(col0 + lmW)*ldw + k0 + kqW;
    const int m0 = (tid >> 4) << 3;
    const int n0 = (tid & 15) << 2;
    u64t acc[4][4];
    #pragma unroll
    for (int i = 0; i < 4; i++)
        #pragma unroll
        for (int j = 0; j < 4; j++) acc[i][j] = 0ull;

    float4 a0 = *(const float4*)Ag;
    float4 a1 = *(const float4*)(Ag + 4);
    float4 w0 = *(const float4*)Wg;

    __syncthreads();

    for (int it = 0; it < niter; it++) {
        const int bA = (it & 1) * (16*132);
        const int bW = (it & 1) * (16*68);
        As[bA+(kqA+0)*132+lmA]=a0.x; As[bA+(kqA+1)*132+lmA]=a0.y;
        As[bA+(kqA+2)*132+lmA]=a0.z; As[bA+(kqA+3)*132+lmA]=a0.w;
        As[bA+(kqA+4)*132+lmA]=a1.x; As[bA+(kqA+5)*132+lmA]=a1.y;
        As[bA+(kqA+6)*132+lmA]=a1.z; As[bA+(kqA+7)*132+lmA]=a1.w;
        Ws[bW+(kqW+0)*68+lmW]=w0.x; Ws[bW+(kqW+1)*68+lmW]=w0.y;
        Ws[bW+(kqW+2)*68+lmW]=w0.z; Ws[bW+(kqW+3)*68+lmW]=w0.w;
        __syncthreads();
        if (it + 1 < niter) {
            const float* An = Ag + (it+1)*16;
            a0 = *(const float4*)An; a1 = *(const float4*)(An + 4);
            w0 = *(const float4*)(Wg + (it+1)*16);
        }
        #pragma unroll
        for (int kk = 0; kk < 16; kk++) {
            const float* ar = As + bA + kk*132 + m0;
            ulonglong2 A0 = *(const ulonglong2*)ar;
            ulonglong2 A1 = *(const ulonglong2*)(ar + 4);
            float4 xw = *(const float4*)(Ws + bW + kk*68 + n0);
            u64t W0 = dup2(xw.x), W1 = dup2(xw.y), W2 = dup2(xw.z), W3 = dup2(xw.w);
            fma2(acc[0][0], A0.x, W0); fma2(acc[0][1], A0.x, W1);
            fma2(acc[0][2], A0.x, W2); fma2(acc[0][3], A0.x, W3);
            fma2(acc[1][0], A0.y, W0); fma2(acc[1][1], A0.y, W1);
            fma2(acc[1][2], A0.y, W2); fma2(acc[1][3], A0.y, W3);
            fma2(acc[2][0], A1.x, W0); fma2(acc[2][1], A1.x, W1);
            fma2(acc[2][2], A1.x, W2); fma2(acc[2][3], A1.x, W3);
            fma2(acc[3][0], A1.y, W0); fma2(acc[3][1], A1.y, W1);
            fma2(acc[3][2], A1.y, W2); fma2(acc[3][3], A1.y, W3);
        }
    }

    #pragma unroll
    for (int i = 0; i < 4; i++) {
        float lo[4], hi[4];
        #pragma unroll
        for (int j = 0; j < 4; j++) upk2(acc[i][j], lo[j], hi[j]);
        size_t r0 = (size_t)(m0 + 2*i) * ldc + col0 + n0;
        size_t r1 = r0 + ldc;
        float4 v = make_float4(lo[0],lo[1],lo[2],lo[3]);
        float4 u = make_float4(hi[0],hi[1],hi[2],hi[3]);
        if (EPI == 1) {
            float4 bb = *(const float4*)(ex + col0 + n0);
            v.x+=bb.x; v.y+=bb.y; v.z+=bb.z; v.w+=bb.w;
            u.x+=bb.x; u.y+=bb.y; u.z+=bb.z; u.w+=bb.w;
        }
        *(float4*)(C + r0) = v;
        *(float4*)(C + r1) = u;
    }
}

template<int EPI>
__global__ void __launch_bounds__(256, 2) gemmP(
    const float* __restrict__ A, int lda, const float* __restrict__ W,
    float* __restrict__ C, int N, int K, const float* __restrict__ bias)
{
    __shared__ __align__(16) float As[2*16*132];
    __shared__ __align__(16) float Ws[2*16*68];
    dgL<EPI>(A + (size_t)blockIdx.y*128*lda, lda, W, K,
             C + (size_t)blockIdx.y*128*N, N,
             blockIdx.x*64, 0, K/16, bias, As, Ws);
}

// ================= compacted loop GEMM tile: M=64 (gathered rows) x N=128 =================
// Same inner issue mix & per-element K order as dgL (16 FMA2 + 3 LDS + 4 MOV / kk).
// A rows gathered via list[mtile*64 + r]; C written at compact rows mtile*64+r.
// EPI: 0 plain, 2 +ex[compact C-indexed]
template<int EPI>
__device__ __noinline__ void dgLc(
    const float* __restrict__ A, int lda, const int* __restrict__ list, int mtile,
    const float* __restrict__ W, int ldw,
    float* __restrict__ C, int ldc,
    int col0, int k0, int niter,
    const float* __restrict__ ex,
    float* __restrict__ As, float* __restrict__ Ws)
{
    const int tid = threadIdx.x;
    const int lmA = tid >> 2, kqA = (tid & 3) << 2;   // A tile: 64 rows x 16k
    const int lmW = tid >> 1, kqW = (tid & 1) << 3;   // W tile: 128 rows x 16k
    const int arow = list[mtile*64 + lmA];
    const float* Ag = A + (size_t)arow*lda + k0 + kqA;
    const float* Wg = W + (size_t)(col0 + lmW)*ldw + k0 + kqW;
    const int m0 = (tid >> 5) << 3;   // 8 m-groups x 8 rows
    const int n0 = (tid & 31) << 2;   // 32 n-groups x 4 cols
    u64t acc[4][4];
    #pragma unroll
    for (int i = 0; i < 4; i++)
        #pragma unroll
        for (int j = 0; j < 4; j++) acc[i][j] = 0ull;

    float4 a0 = *(const float4*)Ag;
    float4 w0 = *(const float4*)Wg;
    float4 w1 = *(const float4*)(Wg + 4);

    __syncthreads();

    for (int it = 0; it < niter; it++) {
        const int bA = (it & 1) * (16*68);
        const int bW = (it & 1) * (16*132);
        As[bA+(kqA+0)*68+lmA]=a0.x; As[bA+(kqA+1)*68+lmA]=a0.y;
        As[bA+(kqA+2)*68+lmA]=a0.z; As[bA+(kqA+3)*68+lmA]=a0.w;
        Ws[bW+(kqW+0)*132+lmW]=w0.x; Ws[bW+(kqW+1)*132+lmW]=w0.y;
        Ws[bW+(kqW+2)*132+lmW]=w0.z; Ws[bW+(kqW+3)*132+lmW]=w0.w;
        Ws[bW+(kqW+4)*132+lmW]=w1.x; Ws[bW+(kqW+5)*132+lmW]=w1.y;
        Ws[bW+(kqW+6)*132+lmW]=w1.z; Ws[bW+(kqW+7)*132+lmW]=w1.w;
        __syncthreads();
        if (it + 1 < niter) {
            a0 = *(const float4*)(Ag + (it+1)*16);
            const float* Wn = Wg + (it+1)*16;
            w0 = *(const float4*)Wn; w1 = *(const float4*)(Wn + 4);
        }
        #pragma unroll
        for (int kk = 0; kk < 16; kk++) {
            const float* ar = As + bA + kk*68 + m0;
            ulonglong2 A0 = *(const ulonglong2*)ar;        // rows (m0,m0+1),(m0+2,m0+3)
            ulonglong2 A1 = *(const ulonglong2*)(ar + 4);  // rows (m0+4..m0+7)
            float4 xw = *(const float4*)(Ws + bW + kk*132 + n0);
            u64t W0 = dup2(xw.x), W1 = dup2(xw.y), W2 = dup2(xw.z), W3 = dup2(xw.w);
            fma2(acc[0][0], A0.x, W0); fma2(acc[0][1], A0.x, W1);
            fma2(acc[0][2], A0.x, W2); fma2(acc[0][3], A0.x, W3);
            fma2(acc[1][0], A0.y, W0); fma2(acc[1][1], A0.y, W1);
            fma2(acc[1][2], A0.y, W2); fma2(acc[1][3], A0.y, W3);
            fma2(acc[2][0], A1.x, W0); fma2(acc[2][1], A1.x, W1);
            fma2(acc[2][2], A1.x, W2); fma2(acc[2][3], A1.x, W3);
            fma2(acc[3][0], A1.y, W0); fma2(acc[3][1], A1.y, W1);
            fma2(acc[3][2], A1.y, W2); fma2(acc[3][3], A1.y, W3);
        }
    }

    #pragma unroll
    for (int i = 0; i < 4; i++) {
        float lo[4], hi[4];
        #pragma unroll
        for (int j = 0; j < 4; j++) upk2(acc[i][j], lo[j], hi[j]);
        size_t r0 = (size_t)(mtile*64 + m0 + 2*i) * ldc + col0 + n0;
        size_t r1 = r0 + ldc;
        float4 v = make_float4(lo[0],lo[1],lo[2],lo[3]);
        float4 u = make_float4(hi[0],hi[1],hi[2],hi[3]);
        if (EPI == 2) {
            float4 e0 = *(const float4*)(ex + r0);
            float4 e1 = *(const float4*)(ex + r1);
            v.x+=e0.x; v.y+=e0.y; v.z+=e0.z; v.w+=e0.w;
            u.x+=e1.x; u.y+=e1.y; u.z+=e1.z; u.w+=e1.w;
        }
        *(float4*)(C + r0) = v;
        *(float4*)(C + r1) = u;
    }
}

// ---------------- prep + embed (unchanged) ----------------
__global__ void k_prep(const float* __restrict__ vs, const float* __restrict__ Wsi,
                       const float* __restrict__ Wsh, const float* __restrict__ b_bd)
{
    int i = blockIdx.x;
    __shared__ float red[256];
    float acc = 0.f;
    if (i < FT) {
        for (int j = threadIdx.x; j < MD; j += 256) acc += vs[j] * Wsi[(size_t)j*FT + i];
    } else if (i < FT + HH) {
        int h = i - FT;
        for (int j = threadIdx.x; j < MD; j += 256) acc += vs[j] * Wsh[(size_t)j*HH + h];
    } else {
        for (int j = threadIdx.x; j < MD; j += 256) acc += vs[j] * b_bd[j];
    }
    red[threadIdx.x] = acc; __syncthreads();
    for (int off = 128; off; off >>= 1) {
        if (threadIdx.x < off) red[threadIdx.x] += red[threadIdx.x + off];
        __syncthreads();
    }
    if (threadIdx.x == 0) {
        if (i < FT) g_w[i] = red[0];
        else if (i < FT + HH) g_u[i - FT] = red[0];
        else g_c0[0] = red[0];
    }
}

__global__ void k_embed(const int* __restrict__ enc, const int* __restrict__ encx,
                        const float* __restrict__ wemb, const float* __restrict__ xemb)
{
    int n = blockIdx.x;
    int t = n >> 7;
    int b = n & 127;
    int w = enc [b*SL + t];
    int e = encx[b*SL + t];
    float4* dst = (float4*)(g_X + (size_t)n*FT);
    const float4* ws = (const float4*)(wemb + (size_t)w*512);
    const float4* xs = (const float4*)(xemb + (size_t)e*64);
    const float4* w4 = (const float4*)g_w;
    float dot = 0.f;
    for (int i = threadIdx.x; i < 128; i += 128) {
        float4 v = ws[i]; dst[i] = v;
        float4 c = w4[i];
        dot += v.x*c.x + v.y*c.y + v.z*c.z + v.w*c.w;
    }
    for (int i = threadIdx.x; i < 16; i += 128) {
        float4 v = xs[i]; dst[128 + i] = v;
        float4 c = w4[128 + i];
        dot += v.x*c.x + v.y*c.y + v.z*c.z + v.w*c.w;
    }
    __shared__ float red[128];
    red[threadIdx.x] = dot; __syncthreads();
    for (int off = 64; off; off >>= 1) {
        if (threadIdx.x < off) red[threadIdx.x] += red[threadIdx.x + off];
        __syncthreads();
    }
    if (threadIdx.x == 0) g_d[n] = red[0] + g_c0[0];
}

__global__ void k_init()
{
    int i = threadIdx.x;
    g_iden[i] = i;
    g_pos1[0][i] = -1; g_pos1[1][i] = -1;
    g_pos2[0][i] = -1; g_pos2[1][i] = -1;
    if (i == 0) { g_n1[0]=0; g_n1[1]=0; g_n2[0]=0; g_n2[1]=0; }
}

// ---------------- elementwise items ----------------
__device__ __forceinline__ float4 f4add(float4 a, float4 b) {
    return make_float4(a.x+b.x, a.y+b.y, a.z+b.z, a.w+b.w);
}

// m1 compact row c belongs to batch b: m1c[c] = pre_mx[b] * sum_kc m1P[kc][c]
__device__ void fin_m1c(int c, int b, const float* __restrict__ pre_mx)
{
    const float4* P = (const float4*)g_m1P;
    int idx = c*256 + threadIdx.x;
    float4 s = make_float4(0.f,0.f,0.f,0.f);
    #pragma unroll
    for (int ch = 0; ch < 16; ch++) s = f4add(s, P[(size_t)ch*32768 + idx]);
    float4 m = ((const float4*)(g_pmx))[0];  // placeholder avoided below
    m = ((const float4*)pre_mx)[(size_t)b*256 + threadIdx.x];
    ((float4*)g_m1)[idx] = make_float4(s.x*m.x, s.y*m.y, s.z*m.z, s.w*m.w);
}

__device__ void fin_m2c(int c)
{
    const float4* P = (const float4*)g_m2xP;
    const float4* T = (const float4*)g_t2P;
    int idx = c*256 + threadIdx.x;
    float4 s = make_float4(0.f,0.f,0.f,0.f);
    float4 u = make_float4(0.f,0.f,0.f,0.f);
    #pragma unroll
    for (int ch = 0; ch < 16; ch++) {
        s = f4add(s, P[(size_t)ch*32768 + idx]);
        u = f4add(u, T[(size_t)ch*32768 + idx]);
    }
    ((float4*)g_m2)[idx] = make_float4(s.x*u.x, s.y*u.y, s.z*u.z, s.w*u.w);
}

__device__ void gate1_b(int b, const float* __restrict__ pre_ih, const int* __restrict__ pos1)
{
    float s = g_s[b];
    int h = threadIdx.x * 4;
    const float* pz = pre_ih + (size_t)b*Z4;
    float4 zi = *(const float4*)(pz + h);
    float4 zf = *(const float4*)(pz + HH + h);
    float4 zg = *(const float4*)(pz + 2*HH + h);
    float4 zo = *(const float4*)(pz + 3*HH + h);
    int p = pos1[b];
    if (p >= 0) {
        #pragma unroll
        for (int c = 0; c < 8; c++) {
            const float* pp = g_z1P + (size_t)c*BB*Z4 + (size_t)p*Z4;
            zi = f4add(zi, *(const float4*)(pp + h));
            zf = f4add(zf, *(const float4*)(pp + HH + h));
            zg = f4add(zg, *(const float4*)(pp + 2*HH + h));
            zo = f4add(zo, *(const float4*)(pp + 3*HH + h));
        }
    }
    int base = b*HH + h;
    float4 c1 = *(const float4*)(g_c1 + base);
    float4 cn, hn;
    cn.x = sigf(zf.x)*c1.x + sigf(zi.x)*tanhf(zg.x);
    cn.y = sigf(zf.y)*c1.y + sigf(zi.y)*tanhf(zg.y);
    cn.z = sigf(zf.z)*c1.z + sigf(zi.z)*tanhf(zg.z);
    cn.w = sigf(zf.w)*c1.w + sigf(zi.w)*tanhf(zg.w);
    hn.x = sigf(zo.x)*tanhf(cn.x);
    hn.y = sigf(zo.y)*tanhf(cn.y);
    hn.z = sigf(zo.z)*tanhf(cn.z);
    hn.w = sigf(zo.w)*tanhf(cn.w);
    float om = 1.f - s;
    *(float4*)(g_x2 + base) = make_float4(hn.x*s, hn.y*s, hn.z*s, hn.w*s);
    *(float4*)(g_h1 + base) = make_float4(hn.x*om, hn.y*om, hn.z*om, hn.w*om);
    *(float4*)(g_c1 + base) = make_float4(cn.x*om, cn.y*om, cn.z*om, cn.w*om);
}

__device__ void gate2out4(int t, int g, float* __restrict__ out,
                          const float* __restrict__ b2, const int* __restrict__ pos2, bool fin)
{
    bool upd = g_flagbuf[t & 1] > 0.5f;
    int b0 = g*4;
    int h = threadIdx.x * 4;
    for (int b = b0; b < b0+4; b++) {
        int base = b*HH + h;
        float4 hv, cv;
        if (upd) {
            float4 zi = *(const float4*)(b2 + h);
            float4 zf = *(const float4*)(b2 + HH + h);
            float4 zg = *(const float4*)(b2 + 2*HH + h);
            float4 zo = *(const float4*)(b2 + 3*HH + h);
            int p = pos2[b];
            if (p >= 0) {
                #pragma unroll
                for (int c = 0; c < 8; c++) {
                    const float* pp = g_z2bP + (size_t)c*BB*Z4 + (size_t)p*Z4;
                    zi = f4add(zi, *(const float4*)(pp + h));
                    zf = f4add(zf, *(const float4*)(pp + HH + h));
                    zg = f4add(zg, *(const float4*)(pp + 2*HH + h));
                    zo = f4add(zo, *(const float4*)(pp + 3*HH + h));
                }
            }
            float4 c2 = *(const float4*)(g_c2 + base);
            cv.x = sigf(zf.x)*c2.x + sigf(zi.x)*tanhf(zg.x);
            cv.y = sigf(zf.y)*c2.y + sigf(zi.y)*tanhf(zg.y);
            cv.z = sigf(zf.z)*c2.z + sigf(zi.z)*tanhf(zg.z);
            cv.w = sigf(zf.w)*c2.w + sigf(zi.w)*tanhf(zg.w);
            hv.x = sigf(zo.x)*tanhf(cv.x);
            hv.y = sigf(zo.y)*tanhf(cv.y);
            hv.z = sigf(zo.z)*tanhf(cv.z);
            hv.w = sigf(zo.w)*tanhf(cv.w);
            *(float4*)(g_c2 + base) = cv;
            *(float4*)(g_h2 + base) = hv;
        } else {
            hv = *(const float4*)(g_h2 + base);
            cv = *(const float4*)(g_c2 + base);
        }
        *(float4*)(out + (size_t)b*SL*HH + (size_t)t*HH + h) = hv;
        if (fin) {
            size_t off = (size_t)BB*SL*HH;
            *(float4*)(out + off + base) = hv;
            *(float4*)(out + off + (size_t)BB*HH + base) = cv;
        }
    }
}

__device__ void sdot16(int t, int k, float* __restrict__ out)
{
    int warp = threadIdx.x >> 5, lane = threadIdx.x & 31;
    int base = k*16 + warp*2;
    for (int bi = 0; bi < 2; bi++) {
        int b = base + bi;
        const float* hp = g_h1 + (size_t)b*HH;
        float p = 0.f;
        for (int j = lane; j < HH; j += 32) p += hp[j] * g_u[j];
        #pragma unroll
        for (int o = 16; o; o >>= 1) p += __shfl_xor_sync(0xffffffffu, p, o);
        if (lane == 0) {
            float sv = (p + g_d[(size_t)t*BB + b] > 0.f) ? 1.f : 0.f;
            g_s[b] = sv;
            if (b == 0) {
                g_flagbuf[t & 1] = sv;
                out[(size_t)BB*SL*HH + 2*(size_t)BB*HH + t] = sv;
            }
        }
    }
}

// build act2(t) [parity t&1] and act1(t+1) [parity (t+1)&1] from g_s
__device__ void build_lists(int t)
{
    if (threadIdx.x == 0) {
        int q = t & 1, p = (t + 1) & 1;
        int n1 = 0, n2 = 0;
        for (int b = 0; b < BB; b++) {
            if (g_s[b] > 0.5f) {
                g_act2[q][n2] = b; g_pos2[q][b] = n2; n2++;
                g_pos1[p][b] = -1;
            } else {
                g_act1[p][n1] = b; g_pos1[p][b] = n1; n1++;
                g_pos2[q][b] = -1;
            }
        }
        g_n1[p] = n1; g_n2[q] = n2;
        int n1p = (n1 + 63) & ~63, n2p = (n2 + 63) & ~63;
        for (int i = n1; i < n1p; i++) g_act1[p][i] = 0;
        for (int i = n2; i < n2p; i++) g_act2[q][i] = 0;
    }
}

// ---------------- persistent recurrent-loop kernel (2 CTAs/SM) ----------------
__global__ void __launch_bounds__(256, 2) k_loop(
    const float* __restrict__ Wmh1, const float* __restrict__ Whh1,
    const float* __restrict__ Wmx2, const float* __restrict__ Wmh2,
    const float* __restrict__ Wih2, const float* __restrict__ Whh2,
    const float* __restrict__ b2, float* __restrict__ out)
{
    __shared__ __align__(16) float As[2*16*68];
    __shared__ __align__(16) float Ws[2*16*132];
    const int bid = blockIdx.x;
    const unsigned G = gridDim.x;

    for (int t = 0; t < SL; t++) {
        const int par = t & 1;
        const float* pre_mx = g_pmx + (size_t)t*BB*HH;
        const float* pre_ih = g_pih + (size_t)t*BB*Z4;
        const int* act1 = g_act1[par];
        int n1 = g_n1[par];
        int nMt1 = (n1 + 63) >> 6;
        int nm1 = nMt1 << 7;   // m1 items

        // Phase A: m1 partials (nMt1*128) | gate2out(t-1) (32) | sdot (8)   <= 296
        for (int it = bid; it < nm1 + 40; it += G) {
            if (it < nm1) {
                int mt = it >> 7, r = it & 127, nt = r >> 4, kc = r & 15;
                dgLc<0>(g_h1, HH, act1, mt, Wmh1, HH,
                        g_m1P + (size_t)kc*BB*HH, HH, nt*128, kc*64, 4, nullptr, As, Ws);
            } else if (it < nm1 + 32) {
                if (t > 0) gate2out4(t-1, it-nm1, out, b2, g_pos2[(t-1)&1], false);
            } else
                sdot16(t, it-nm1-32, out);
        }
        gsync(G);

        // Phase A2: fin_m1 (compact rows < n1) + list building
        for (int it = bid; it < 129; it += G) {
            if (it < 128) { if (it < n1) fin_m1c(it, act1[it], pre_mx); }
            else build_lists(t);
        }
        gsync(G);

        float flag = g_flagbuf[par];
        const int* act2 = g_act2[par];
        int n2 = g_n2[par];
        int nMt2 = (n2 + 63) >> 6;
        int nz1 = nMt1 << 8;
        int nB = nz1 + ((flag > 0.5f) ? (nMt2 << 7) : 0);

        // Phase B: z1 partials | t2 partials (flag)
        for (int it = bid; it < nB; it += G) {
            if (it < nz1) {
                int mt = it >> 8, r = it & 255, nt = r >> 3, kc = r & 7;
                dgLc<0>(g_m1, HH, g_iden, mt, Whh1, HH,
                        g_z1P + (size_t)kc*BB*Z4, Z4, nt*128, kc*128, 8, nullptr, As, Ws);
            } else {
                int j = it - nz1, mt = j >> 7, r = j & 127, nt = r >> 4, kc = r & 15;
                dgLc<0>(g_h2, HH, act2, mt, Wmh2, HH,
                        g_t2P + (size_t)kc*BB*HH, HH, nt*128, kc*64, 4, nullptr, As, Ws);
            }
        }
        gsync(G);

        // Phase C: gate1 (128 items)
        for (int it = bid; it < 128; it += G) gate1_b(it, pre_ih, g_pos1[par]);
        gsync(G);

        if (flag > 0.5f) {
            int nza = nMt2 << 8;
            int nD = nza + (nMt2 << 7);
            // Phase D: z2a partials | m2x partials
            for (int it = bid; it < nD; it += G) {
                if (it < nza) {
                    int mt = it >> 8, r = it & 255, nt = r >> 3, kc = r & 7;
                    dgLc<0>(g_x2, HH, act2, mt, Wih2, HH,
                            g_z2aP + (size_t)kc*BB*Z4, Z4, nt*128, kc*128, 8, nullptr, As, Ws);
                } else {
                    int j = it - nza, mt = j >> 7, r = j & 127, nt = r >> 4, kc = r & 15;
                    dgLc<0>(g_x2, HH, act2, mt, Wmx2, HH,
                            g_m2xP + (size_t)kc*BB*HH, HH, nt*128, kc*64, 4, nullptr, As, Ws);
                }
            }
            gsync(G);
            // Phase D2: m2 compact
            for (int it = bid; it < 128; it += G) if (it < n2) fin_m2c(it);
            gsync(G);
            // Phase E: z2bP = m2c@Whh2^T partial + z2aP
            int nE = nMt2 << 8;
            for (int it = bid; it < nE; it += G) {
                int mt = it >> 8, r = it & 255, nt = r >> 3, kc = r & 7;
                dgLc<2>(g_m2, HH, g_iden, mt, Whh2, HH,
                        g_z2bP + (size_t)kc*BB*Z4, Z4, nt*128, kc*128, 8,
                        g_z2aP + (size_t)kc*BB*Z4, As, Ws);
            }
            gsync(G);
        }
    }

    // final step outputs + final states
    for (int it = bid; it < 32; it += (int)G)
        gate2out4(SL-1, it, out, b2, g_pos2[(SL-1)&1], true);
}

// ---------------- host ----------------
extern "C" void kernel_launch(void* const* d_in, const int* in_sizes, int n_in,
                              void* d_out, int out_size)
{
    const int*   enc  = (const int*)  d_in[0];
    const int*   encx = (const int*)  d_in[1];
    const float* wemb = (const float*)d_in[2];
    const float* xemb = (const float*)d_in[3];
    const float* Wsi  = (const float*)d_in[4];
    const float* Wsh  = (const float*)d_in[5];
    const float* b_bd = (const float*)d_in[6];
    const float* vs   = (const float*)d_in[7];
    const float* Wmx1 = (const float*)d_in[8];
    const float* Wmh1 = (const float*)d_in[9];
    const float* Wih1 = (const float*)d_in[10];
    const float* Whh1 = (const float*)d_in[11];
    const float* b1   = (const float*)d_in[12];
    const float* Wmx2 = (const float*)d_in[13];
    const float* Wmh2 = (const float*)d_in[14];
    const float* Wih2 = (const float*)d_in[15];
    const float* Whh2 = (const float*)d_in[16];
    const float* b2   = (const float*)d_in[17];
    float* out = (float*)d_out;

    float *pX, *pmx, *pih, *ph1, *pc1, *ph2, *pc2;
    cudaGetSymbolAddress((void**)&pX,  g_X);
    cudaGetSymbolAddress((void**)&pmx, g_pmx);
    cudaGetSymbolAddress((void**)&pih, g_pih);
    cudaGetSymbolAddress((void**)&ph1, g_h1);
    cudaGetSymbolAddress((void**)&pc1, g_c1);
    cudaGetSymbolAddress((void**)&ph2, g_h2);
    cudaGetSymbolAddress((void**)&pc2, g_c2);

    cudaMemsetAsync(ph1, 0, (size_t)BB*HH*sizeof(float));
    cudaMemsetAsync(pc1, 0, (size_t)BB*HH*sizeof(float));
    cudaMemsetAsync(ph2, 0, (size_t)BB*HH*sizeof(float));
    cudaMemsetAsync(pc2, 0, (size_t)BB*HH*sizeof(float));

    // precompute + init
    k_init<<<1, 128>>>();
    k_prep<<<FT + HH + 1, 256>>>(vs, Wsi, Wsh, b_bd);
    k_embed<<<NT, 128>>>(enc, encx, wemb, xemb);
    gemmP<0><<<dim3(HH/64, NT/128), 256>>>(pX, FT, Wmx1, pmx, HH, FT, nullptr);
    gemmP<1><<<dim3(Z4/64, NT/128), 256>>>(pX, FT, Wih1, pih, Z4, FT, b1);

    // recurrent loop: one persistent kernel, 2 CTAs/SM
    k_loop<<<G2, 256>>>(Wmh1, Whh1, Wmx2, Wmh2, Wih2, Whh2, b2, out);
}